// round 13
// baseline (speedup 1.0000x reference)
#include <cuda_runtime.h>
#include <cuda_bf16.h>

// Problem constants
#define NBATCH 8
#define CIN    8
#define COUT   16
#define HW     65536        // 256*256
#define NPAR   (COUT * CIN) // 128

typedef unsigned long long ull;

// ---- Packed f32x2 helpers (Blackwell native) ----
__device__ __forceinline__ ull add2(ull a, ull b) {
    ull d; asm("add.rn.f32x2 %0, %1, %2;" : "=l"(d) : "l"(a), "l"(b)); return d;
}
__device__ __forceinline__ ull mul2(ull a, ull b) {
    ull d; asm("mul.rn.f32x2 %0, %1, %2;" : "=l"(d) : "l"(a), "l"(b)); return d;
}
__device__ __forceinline__ ull pack2(float lo, float hi) {
    ull r; asm("mov.b64 %0, {%1, %2};" : "=l"(r) : "f"(lo), "f"(hi)); return r;
}
__device__ __forceinline__ void unpack2(ull v, float& lo, float& hi) {
    asm("mov.b64 {%0, %1}, %2;" : "=f"(lo), "=f"(hi) : "l"(v));
}
__device__ __forceinline__ float ex2f(float v) {
    float r; asm("ex2.approx.f32 %0, %1;" : "=f"(r) : "f"(v)); return r;
}

// Per-(o,j): exp(-(x-c)^2/(2w^2)) = ex2( ((x-c)*a) * (x-c) ),  a = -log2(e)/(2w^2)
// Shared stores PRE-SPLATTED packed params {(-c,-c), (a,a)} (16 B): one
// LDS.128 per (o,j) whose 64-bit halves feed f32x2 ops directly (no MOVs).
__global__ __launch_bounds__(128, 8) void soft_hist_kernel(
    const float* __restrict__ x,        // [B][CIN][HW]
    const float* __restrict__ centers,  // [COUT][CIN]
    const float* __restrict__ widths,   // [COUT][CIN]
    float*       __restrict__ out)      // [B][COUT][HW]
{
    __shared__ ulonglong2 sp[NPAR];     // {cc, aa}
    int t = threadIdx.x;
    if (t < NPAR) {
        float c = centers[t];
        float w = widths[t];
        float a = -0.72134752044448170f / (w * w);   // -log2(e)/2 / w^2
        sp[t] = make_ulonglong2(pack2(-c, -c), pack2(a, a));
    }
    __syncthreads();

    // Each thread handles 4 consecutive spatial positions (two packed f32x2).
    int gv  = blockIdx.x * 128 + t;            // quad index in [0, B*HW/4)
    int b   = gv >> 14;                        // 16384 quads per image
    int pos = (gv << 2) & (HW - 1);            // element offset within the image

    int xoff = b * (CIN * HW) + pos;
    int ooff = b * (COUT * HW) + pos;

    // Load 8 input channels x 4 positions (LDG.128 each, independent -> MLP=8).
    ull xv[CIN][2];
    #pragma unroll
    for (int j = 0; j < CIN; j++) {
        ulonglong2 v = *(const ulonglong2*)(x + xoff + j * HW);
        xv[j][0] = v.x;
        xv[j][1] = v.y;
    }

    #pragma unroll
    for (int o = 0; o < COUT; o++) {
        float s0 = 0.0f, s1 = 0.0f, s2 = 0.0f, s3 = 0.0f;
        #pragma unroll
        for (int j = 0; j < CIN; j++) {
            ulonglong2 p = sp[o * CIN + j];    // LDS.128 broadcast: {cc, aa}
            ull d0 = add2(xv[j][0], p.x);      // x - c   (positions 0,1)
            ull d1 = add2(xv[j][1], p.x);      // x - c   (positions 2,3)
            ull t0 = mul2(d0, p.y);            // (x-c)*a
            ull t1 = mul2(d1, p.y);
            ull q0 = mul2(t0, d0);             // (x-c)^2*a
            ull q1 = mul2(t1, d1);
            float a0, a1, a2, a3;
            unpack2(q0, a0, a1);
            unpack2(q1, a2, a3);
            s0 += ex2f(a0);
            s1 += ex2f(a1);
            s2 += ex2f(a2);
            s3 += ex2f(a3);
        }
        *(float4*)(out + ooff + o * HW) = make_float4(s0, s1, s2, s3);
    }
}

extern "C" void kernel_launch(void* const* d_in, const int* in_sizes, int n_in,
                              void* d_out, int out_size) {
    const float* x       = (const float*)d_in[0];   // [8,8,256,256]
    const float* centers = (const float*)d_in[1];   // [16,8]
    const float* widths  = (const float*)d_in[2];   // [16,8]
    float* out = (float*)d_out;                     // [8,16,256,256]

    const int quads = NBATCH * HW / 4;              // 131072
    const int block = 128;
    const int grid  = quads / block;                // 1024
    soft_hist_kernel<<<grid, block>>>(x, centers, widths, out);
}